// round 14
// baseline (speedup 1.0000x reference)
#include <cuda_runtime.h>
#include <cuda_bf16.h>
#include <cstdint>

#define B_MAX 16384

// ---------------- persistent scratch (__device__ globals; no allocations) ----
__device__ int   g_w2I[1024 * 64];    // snn_w2 transposed+paired, fixed-point 2^24:
                                      //   [h][2l]   = w2[l][h]     (output l)
                                      //   [h][2l+1] = w2[l+32][h]  (output l+32)
__device__ float g_nnw2T[1024 * 64];  // nn_w2 transposed: [h][o]
__device__ float g_fcT[1600 * 256];   // cnn_fc_w transposed: [k][o]
__device__ float g_combT[384 * 64];   // comb_w transposed: [c][o]
__device__ float g_snn[B_MAX * 64];
__device__ float g_nn[B_MAX * 64];
__device__ float g_cnn[B_MAX * 256];

#define W2_SCALE    16777216.0f       // 2^24
#define W2_INVSCALE 5.9604645e-8f     // 2^-24

// ---------------- weight transpose / packing ---------------------------------
__global__ void prep_kernel(const float* __restrict__ snn_w2,
                            const float* __restrict__ nn_w2,
                            const float* __restrict__ fc_w,
                            const float* __restrict__ comb_w) {
    int i = blockIdx.x * blockDim.x + threadIdx.x;
    if (i < 1024 * 64) {
        int h = i >> 6, q = i & 63;
        int l = q >> 1;
        int o = (q & 1) ? (l + 32) : l;           // pair (l, l+32) contiguous
        g_w2I[i]   = __float2int_rn(snn_w2[o * 1024 + h] * W2_SCALE);
        g_nnw2T[i] = nn_w2[(i & 63) * 1024 + h];
    }
    if (i < 1600 * 256) {
        int k = i >> 8, o = i & 255;
        g_fcT[i] = fc_w[o * 1600 + k];
    }
    if (i < 384 * 64) {
        int c = i >> 6, o = i & 63;
        g_combT[i] = comb_w[o * 384 + c];
    }
}

// ---------------- SNN: one block (1024 thr) per batch row --------------------
// (unchanged from R12: measured ~830us; conflict-free ATOMS.32 scatter,
// fixed-point 2^24 -> deterministic, rel_err 5.4e-7)
__global__ __launch_bounds__(1024, 2) void snn_kernel(const float* __restrict__ x,
                                                      const float* __restrict__ w1,
                                                      const float* __restrict__ b1,
                                                      const float* __restrict__ b2,
                                                      int B) {
    __shared__ int            s_acc[100 * 64];   // [t][o] fixed-point cur2 accum
    __shared__ uint4          s_train[1024];     // per-active-neuron spike bits
    __shared__ unsigned short s_idx[1024];       // compact -> neuron index
    __shared__ float          s_cval[1024];      // compact -> drive c
    __shared__ unsigned       s_gm[32];
    __shared__ int            s_wbase[32];
    __shared__ int            s_nact;
    __shared__ float          s_feats[5];

    int b   = blockIdx.x;
    int tid = threadIdx.x;
    int wid = tid >> 5;
    int l   = tid & 31;

    if (tid < 5) s_feats[tid] = x[b * 105 + tid];
    __syncthreads();

    // ---- drive c per neuron + compaction (deterministic prefix) ----
    float f0 = s_feats[0], f1 = s_feats[1], f2 = s_feats[2],
          f3 = s_feats[3], f4 = s_feats[4];
    const float* wr = w1 + tid * 5;
    float c = b1[tid] + f0 * wr[0] + f1 * wr[1] + f2 * wr[2] + f3 * wr[3] + f4 * wr[4];
    bool act = c > 0.049995f;   // inclusion margin; excluded neurons provably silent
    unsigned gm = __ballot_sync(0xffffffffu, act);
    if (l == 0) s_gm[wid] = gm;

    // zero the cur2 accumulators while compaction data settles
    #pragma unroll
    for (int i = tid; i < 6400; i += 1024) s_acc[i] = 0;
    __syncthreads();

    if (tid < 32) {
        int cnt = __popc(s_gm[tid]);
        int incl = cnt;
        #pragma unroll
        for (int d = 1; d < 32; d <<= 1) {
            int v = __shfl_up_sync(0xffffffffu, incl, d);
            if (tid >= d) incl += v;
        }
        s_wbase[tid] = incl - cnt;
        if (tid == 31) s_nact = incl;
    }
    __syncthreads();
    if (act) {
        int pos = s_wbase[wid] + __popc(gm & ((1u << l) - 1u));
        s_idx[pos]  = (unsigned short)tid;
        s_cval[pos] = c;
    }
    __syncthreads();

    int nact = s_nact;

    // ---- phase 1: LIF dynamics; each active neuron builds its spike train ----
    if (tid < nact) {
        float cc = s_cval[tid];
        float mem = 0.f, sp = 0.f;
        unsigned tr0 = 0, tr1 = 0, tr2 = 0, tr3 = 0;
        #pragma unroll
        for (int u = 0; u < 32; u++) {
            mem = __fmaf_rn(0.95f, mem, cc) - sp;
            bool s = mem > 1.0f; sp = s ? 1.0f : 0.0f;
            tr0 |= ((unsigned)s) << u;
        }
        #pragma unroll
        for (int u = 0; u < 32; u++) {
            mem = __fmaf_rn(0.95f, mem, cc) - sp;
            bool s = mem > 1.0f; sp = s ? 1.0f : 0.0f;
            tr1 |= ((unsigned)s) << u;
        }
        #pragma unroll
        for (int u = 0; u < 32; u++) {
            mem = __fmaf_rn(0.95f, mem, cc) - sp;
            bool s = mem > 1.0f; sp = s ? 1.0f : 0.0f;
            tr2 |= ((unsigned)s) << u;
        }
        #pragma unroll
        for (int u = 0; u < 4; u++) {
            mem = __fmaf_rn(0.95f, mem, cc) - sp;
            bool s = mem > 1.0f; sp = s ? 1.0f : 0.0f;
            tr3 |= ((unsigned)s) << u;
        }
        s_train[tid] = make_uint4(tr0, tr1, tr2, tr3);
    }
    __syncthreads();

    // ---- phase 2: neuron-major scatter, conflict-free atomic addressing ----
    const int2* w2p = (const int2*)g_w2I;   // [h][32] int2 = (out l, out l+32)
    for (int i = wid; i < nact; i += 32) {
        int2 v  = w2p[(unsigned)s_idx[i] * 32 + l];   // one 256B row load per neuron
        uint4 tr = s_train[i];                        // broadcast LDS.128
        unsigned m;
        m = tr.x;
        while (m) {
            int t = __ffs(m) - 1; m &= m - 1;
            atomicAdd(&s_acc[t * 64 + l],      v.x);
            atomicAdd(&s_acc[t * 64 + 32 + l], v.y);
        }
        m = tr.y;
        while (m) {
            int t = 32 + __ffs(m) - 1; m &= m - 1;
            atomicAdd(&s_acc[t * 64 + l],      v.x);
            atomicAdd(&s_acc[t * 64 + 32 + l], v.y);
        }
        m = tr.z;
        while (m) {
            int t = 64 + __ffs(m) - 1; m &= m - 1;
            atomicAdd(&s_acc[t * 64 + l],      v.x);
            atomicAdd(&s_acc[t * 64 + 32 + l], v.y);
        }
        m = tr.w;
        while (m) {
            int t = 96 + __ffs(m) - 1; m &= m - 1;
            atomicAdd(&s_acc[t * 64 + l],      v.x);
            atomicAdd(&s_acc[t * 64 + 32 + l], v.y);
        }
    }
    __syncthreads();

    // ---- phase 3: layer-2 LIF scan + mean ----
    if (tid < 64) {
        float b2o = b2[tid];
        float mem = 0.f, sp = 0.f, sum = 0.f;
        #pragma unroll 4
        for (int t = 0; t < 100; t++) {
            float cur = __fmaf_rn((float)s_acc[t * 64 + tid], W2_INVSCALE, b2o);
            mem = __fmaf_rn(0.95f, mem, cur) - sp;
            bool s = mem > 1.0f;
            sp = s ? 1.0f : 0.0f;
            sum += sp;
        }
        g_snn[b * 64 + tid] = sum * 0.01f;
    }
}

// ---------------- plain MLP: 8 rows per block --------------------------------
__global__ __launch_bounds__(256) void nn_kernel(const float* __restrict__ x,
                                                 const float* __restrict__ w1,
                                                 const float* __restrict__ b1,
                                                 const float* __restrict__ b2,
                                                 int B) {
    __shared__ float s_h[8 * 1024];   // [r][h]
    __shared__ float s_f[8][5];

    int b0  = blockIdx.x * 8;
    int tid = threadIdx.x;

    if (tid < 40) {
        int r = tid / 5, k = tid % 5;
        s_f[r][k] = x[(b0 + r) * 105 + k];
    }
    __syncthreads();

    for (int j = 0; j < 4; j++) {
        int h = tid + 256 * j;
        const float* wr = w1 + h * 5;
        float w0 = wr[0], w1v = wr[1], w2v = wr[2], w3 = wr[3], w4 = wr[4];
        float bb = b1[h];
        #pragma unroll
        for (int r = 0; r < 8; r++) {
            float v = bb + s_f[r][0] * w0 + s_f[r][1] * w1v + s_f[r][2] * w2v +
                      s_f[r][3] * w3 + s_f[r][4] * w4;
            s_h[r * 1024 + h] = v > 0.f ? v : 0.f;
        }
    }
    __syncthreads();

    int o  = tid & 63;
    int rg = tid >> 6;
    float a0 = 0.f, a1 = 0.f;
    const float* h0 = s_h + (rg * 2) * 1024;
    const float* h1 = s_h + (rg * 2 + 1) * 1024;
    for (int h = 0; h < 1024; h++) {
        float w = g_nnw2T[h * 64 + o];
        a0 += w * h0[h];
        a1 += w * h1[h];
    }
    float bo = b2[o];
    g_nn[(b0 + rg * 2) * 64 + o]     = a0 + bo;
    g_nn[(b0 + rg * 2 + 1) * 64 + o] = a1 + bo;
}

// ---------------- CNN: 16 rows/block, 256 thr, 2 outputs/thread, f32x2 FC ----
// (unchanged from R12: measured 289us, fma 60%)
#define CNN_SMEM_BYTES ((25600 + 16 * 102) * 4)

__global__ __launch_bounds__(256, 2) void cnn_kernel(const float* __restrict__ x,
                                                     const float* __restrict__ cw,
                                                     const float* __restrict__ cb,
                                                     const float* __restrict__ fcb,
                                                     int B) {
    extern __shared__ float sm[];
    float* s_p    = sm;            // pooled, transposed: [k=ch*50+j][r] (1600 x 16)
    float* s_wave = sm + 25600;    // [r][102] zero-padded

    __shared__ float s_cw[96];
    __shared__ float s_cb[32];

    int b0  = blockIdx.x * 16;
    int tid = threadIdx.x;

    if (tid < 96) s_cw[tid] = cw[tid];
    if (tid < 32) s_cb[tid] = cb[tid];
    for (int i = tid; i < 16 * 102; i += 256) {
        int r = i / 102, q = i % 102;
        float v = 0.f;
        if (q >= 1 && q <= 100) v = x[(b0 + r) * 105 + 4 + q];
        s_wave[i] = v;
    }
    __syncthreads();

    for (int i = tid; i < 25600; i += 256) {
        int r   = i & 15;
        int pos = i >> 4;
        int ch  = pos / 50;
        int j   = pos - ch * 50;
        const float* wv = s_wave + r * 102 + 2 * j;
        float w0 = s_cw[ch * 3], w1 = s_cw[ch * 3 + 1], w2 = s_cw[ch * 3 + 2];
        float bb = s_cb[ch];
        float c0 = bb + wv[0] * w0 + wv[1] * w1 + wv[2] * w2;
        float c1 = bb + wv[1] * w0 + wv[2] * w1 + wv[3] * w2;
        float m = fmaxf(c0, c1);
        s_p[pos * 16 + r] = m > 0.f ? m : 0.f;
    }
    __syncthreads();

    int og = tid & 127;
    int kh = tid >> 7;
    unsigned long long a[16];
    #pragma unroll
    for (int q = 0; q < 16; q++) a[q] = 0ull;

    int kbeg = kh * 800;
    const float2* fp = (const float2*)g_fcT + (size_t)kbeg * 128 + og;
    const ulonglong2* rp = (const ulonglong2*)s_p + kbeg * 4;

    for (int kk = 0; kk < 800; kk += 4) {
        float2 w0 = fp[0], w1 = fp[128], w2 = fp[256], w3 = fp[384];
        fp += 512;
        unsigned long long W0[4], W1[4];
        asm("mov.b64 %0, {%1, %1};" : "=l"(W0[0]) : "r"(__float_as_uint(w0.x)));
        asm("mov.b64 %0, {%1, %1};" : "=l"(W1[0]) : "r"(__float_as_uint(w0.y)));
        asm("mov.b64 %0, {%1, %1};" : "=l"(W0[1]) : "r"(__float_as_uint(w1.x)));
        asm("mov.b64 %0, {%1, %1};" : "=l"(W1[1]) : "r"(__float_as_uint(w1.y)));
        asm("mov.b64 %0, {%1, %1};" : "=l"(W0[2]) : "r"(__float_as_uint(w2.x)));
        asm("mov.b64 %0, {%1, %1};" : "=l"(W1[2]) : "r"(__float_as_uint(w2.y)));
        asm("mov.b64 %0, {%1, %1};" : "=l"(W0[3]) : "r"(__float_as_uint(w3.x)));
        asm("mov.b64 %0, {%1, %1};" : "=l"(W1[3]) : "r"(__float_as_uint(w3.y)));
        #pragma unroll
        for (int u = 0; u < 4; u++) {
            #pragma unroll
            for (int m2 = 0; m2 < 4; m2++) {
                ulonglong2 v = rp[u * 4 + m2];
                asm("fma.rn.f32x2 %0, %1, %2, %0;" : "+l"(a[2 * m2])         : "l"(v.x), "l"(W0[u]));
                asm("fma.rn.f32x2 %0, %1, %2, %0;" : "+l"(a[2 * m2 + 1])     : "l"(v.y), "l"(W0[u]));
                asm("fma.rn.f32x2 %0, %1, %2, %0;" : "+l"(a[8 + 2 * m2])     : "l"(v.x), "l"(W1[u]));
                asm("fma.rn.f32x2 %0, %1, %2, %0;" : "+l"(a[8 + 2 * m2 + 1]) : "l"(v.y), "l"(W1[u]));
            }
        }
        rp += 16;
    }

    int o0 = og * 2;
    if (kh == 1) {
        #pragma unroll
        for (int q = 0; q < 8; q++) {
            float lo0 = __uint_as_float((unsigned)(a[q] & 0xffffffffull));
            float hi0 = __uint_as_float((unsigned)(a[q] >> 32));
            float lo1 = __uint_as_float((unsigned)(a[8 + q] & 0xffffffffull));
            float hi1 = __uint_as_float((unsigned)(a[8 + q] >> 32));
            *(float2*)(g_cnn + (b0 + 2 * q) * 256 + o0)     = make_float2(lo0, lo1);
            *(float2*)(g_cnn + (b0 + 2 * q + 1) * 256 + o0) = make_float2(hi0, hi1);
        }
    }
    __syncthreads();
    if (kh == 0) {
        float fb0 = fcb[o0], fb1 = fcb[o0 + 1];
        #pragma unroll
        for (int q = 0; q < 8; q++) {
            float lo0 = __uint_as_float((unsigned)(a[q] & 0xffffffffull));
            float hi0 = __uint_as_float((unsigned)(a[q] >> 32));
            float lo1 = __uint_as_float((unsigned)(a[8 + q] & 0xffffffffull));
            float hi1 = __uint_as_float((unsigned)(a[8 + q] >> 32));
            float2* p0 = (float2*)(g_cnn + (b0 + 2 * q) * 256 + o0);
            float2* p1 = (float2*)(g_cnn + (b0 + 2 * q + 1) * 256 + o0);
            float2 v0 = *p0, v1 = *p1;
            *p0 = make_float2(lo0 + fb0 + v0.x, lo1 + fb1 + v0.y);
            *p1 = make_float2(hi0 + fb0 + v1.x, hi1 + fb1 + v1.y);
        }
    }
}

// ---------------- combiner ----------------------------------------------------
__global__ __launch_bounds__(256) void comb_kernel(const float* __restrict__ cbias,
                                                   float* __restrict__ out,
                                                   int B) {
    __shared__ float s_c[16 * 384];   // [r][c]
    int b0  = blockIdx.x * 16;
    int tid = threadIdx.x;

    for (int i = tid; i < 16 * 64; i += 256) {
        int r = i >> 6, o = i & 63;
        s_c[r * 384 + o]      = g_snn[(b0 + r) * 64 + o];
        s_c[r * 384 + 64 + o] = g_nn[(b0 + r) * 64 + o];
    }
    for (int i = tid; i < 16 * 256; i += 256) {
        int r = i >> 8, o = i & 255;
        s_c[r * 384 + 128 + o] = g_cnn[(b0 + r) * 256 + o];
    }
    __syncthreads();

    int o  = tid & 63;
    int rg = tid >> 6;
    float a[4] = {0.f, 0.f, 0.f, 0.f};
    for (int c = 0; c < 384; c++) {
        float w = g_combT[c * 64 + o];
        const float* pr = s_c + (rg * 4) * 384 + c;
        a[0] += w * pr[0];
        a[1] += w * pr[384];
        a[2] += w * pr[2 * 384];
        a[3] += w * pr[3 * 384];
    }
    float bo = cbias[o];
    #pragma unroll
    for (int q = 0; q < 4; q++)
        out[(b0 + rg * 4 + q) * 64 + o] = a[q] + bo;
}

// ---------------- launch -------------------------------------------------------
// Single change vs R12: fork cnn (s1) and nn (s2) onto side streams so they run
// under the snn shadow (snn: smem-atomic bound; cnn: fma bound; nn: LDG-latency
// bound — disjoint resources). comb joins all branches. Event-fork capture
// pattern proven graph-safe in R9.
extern "C" void kernel_launch(void* const* d_in, const int* in_sizes, int n_in,
                              void* d_out, int out_size) {
    const float* x      = (const float*)d_in[0];
    const float* snn_w1 = (const float*)d_in[1];
    const float* snn_b1 = (const float*)d_in[2];
    const float* snn_w2 = (const float*)d_in[3];
    const float* snn_b2 = (const float*)d_in[4];
    const float* nn_w1  = (const float*)d_in[5];
    const float* nn_b1  = (const float*)d_in[6];
    const float* nn_w2  = (const float*)d_in[7];
    const float* nn_b2  = (const float*)d_in[8];
    const float* conv_w = (const float*)d_in[9];
    const float* conv_b = (const float*)d_in[10];
    const float* fc_w   = (const float*)d_in[11];
    const float* fc_b   = (const float*)d_in[12];
    const float* comb_w = (const float*)d_in[13];
    const float* comb_b = (const float*)d_in[14];

    int B = in_sizes[0] / 105;

    static cudaStream_t s1 = nullptr, s2 = nullptr;
    static cudaEvent_t  e0 = nullptr, e1 = nullptr, e2 = nullptr;
    static bool attr_set = false;
    if (!s1) {
        cudaStreamCreateWithFlags(&s1, cudaStreamNonBlocking);
        cudaStreamCreateWithFlags(&s2, cudaStreamNonBlocking);
        cudaEventCreateWithFlags(&e0, cudaEventDisableTiming);
        cudaEventCreateWithFlags(&e1, cudaEventDisableTiming);
        cudaEventCreateWithFlags(&e2, cudaEventDisableTiming);
    }
    if (!attr_set) {
        cudaFuncSetAttribute(cnn_kernel, cudaFuncAttributeMaxDynamicSharedMemorySize,
                             CNN_SMEM_BYTES);
        attr_set = true;
    }

    prep_kernel<<<1600, 256>>>(snn_w2, nn_w2, fc_w, comb_w);
    cudaEventRecord(e0, 0);

    cudaStreamWaitEvent(s1, e0, 0);
    cnn_kernel<<<B / 16, 256, CNN_SMEM_BYTES, s1>>>(x, conv_w, conv_b, fc_b, B);
    cudaEventRecord(e1, s1);

    cudaStreamWaitEvent(s2, e0, 0);
    nn_kernel<<<B / 8, 256, 0, s2>>>(x, nn_w1, nn_b1, nn_b2, B);
    cudaEventRecord(e2, s2);

    snn_kernel<<<B, 1024>>>(x, snn_w1, snn_b1, snn_b2, B);

    cudaStreamWaitEvent(0, e1, 0);
    cudaStreamWaitEvent(0, e2, 0);
    comb_kernel<<<B / 16, 256>>>(comb_b, (float*)d_out, B);
}

// round 15
// speedup vs baseline: 1.0796x; 1.0796x over previous
#include <cuda_runtime.h>
#include <cuda_bf16.h>
#include <cstdint>

#define B_MAX 16384

__device__ int   g_w2Q[1024 * 64];    // [h*64 + r*8 + j] = rn(w2[r+8j][h]*2^24)
__device__ float g_nnw2T[1024 * 64];
__device__ float g_fcT[1600 * 256];
__device__ float g_combT[384 * 64];
__device__ float g_snn[B_MAX * 64];
__device__ float g_nn[B_MAX * 64];
__device__ float g_cnn[B_MAX * 256];

#define W2_SCALE    16777216.0f
#define W2_INVSCALE 5.9604645e-8f

__global__ void prep_kernel(const float* __restrict__ snn_w2,
                            const float* __restrict__ nn_w2,
                            const float* __restrict__ fc_w,
                            const float* __restrict__ comb_w) {
    int i = blockIdx.x * blockDim.x + threadIdx.x;
    if (i < 1024 * 64) {
        int h = i >> 6, j6 = i & 63;
        int o = (j6 >> 3) + 8 * (j6 & 7);
        g_w2Q[i]   = __float2int_rn(snn_w2[o * 1024 + h] * W2_SCALE);
        g_nnw2T[i] = nn_w2[(i & 63) * 1024 + h];
    }
    if (i < 1600 * 256) g_fcT[i] = fc_w[(i & 255) * 1600 + (i >> 8)];
    if (i < 384 * 64)   g_combT[i] = comb_w[(i & 63) * 384 + (i >> 6)];
}

// SNN: quad-neuron scatter. 4 neurons/warp, 8 lanes each; per iteration the
// warp retires 4 spikes (FLO+LOP+VOTE+8 ATOMS). Bucket-sort by spike count
// balances quads. s_acc stride 128 + 8g skew -> all ATOMS 32-bank
// conflict-free; alias columns 64..87 folded in phase 3. Fixed-point sums are
// order-independent -> bit-identical to R12.
#define SNN_SMEM_BYTES (19224 * 4)

__global__ __launch_bounds__(1024, 2) void snn_kernel(const float* __restrict__ x,
                                                      const float* __restrict__ w1,
                                                      const float* __restrict__ b1,
                                                      const float* __restrict__ b2,
                                                      int B) {
    extern __shared__ int dsm[];
    int*            s_acc   = dsm;                            // [100][128]
    uint4*          s_train = (uint4*)(dsm + 12800);          // [1024]
    unsigned short* s_idx   = (unsigned short*)(dsm + 16896); // [1024]
    float*          s_cval  = (float*)(dsm + 17408);          // [1024]
    unsigned short* s_order = (unsigned short*)(dsm + 18432); // [1024]
    int*            s_hist  = dsm + 18944;                    // [104]
    int*            s_cur   = dsm + 19048;                    // [104]
    unsigned*       s_gm    = (unsigned*)(dsm + 19152);
    int*            s_wbase = dsm + 19184;
    int*            s_nactp = dsm + 19216;
    float*          s_feats = (float*)(dsm + 19217);

    int b = blockIdx.x, tid = threadIdx.x, wid = tid >> 5, l = tid & 31;

    if (tid < 5) s_feats[tid] = x[b * 105 + tid];
    __syncthreads();

    float f0 = s_feats[0], f1 = s_feats[1], f2 = s_feats[2],
          f3 = s_feats[3], f4 = s_feats[4];
    const float* wr = w1 + tid * 5;
    float c = b1[tid] + f0 * wr[0] + f1 * wr[1] + f2 * wr[2] + f3 * wr[3] + f4 * wr[4];
    bool act = c > 0.049995f;
    unsigned gm = __ballot_sync(0xffffffffu, act);
    if (l == 0) s_gm[wid] = gm;

    for (int i = tid; i < 12800; i += 1024) s_acc[i] = 0;
    if (tid < 104) s_hist[tid] = 0;
    __syncthreads();

    if (tid < 32) {
        int cnt = __popc(s_gm[tid]);
        int incl = cnt;
        #pragma unroll
        for (int d = 1; d < 32; d <<= 1) {
            int v = __shfl_up_sync(0xffffffffu, incl, d);
            if (tid >= d) incl += v;
        }
        s_wbase[tid] = incl - cnt;
        if (tid == 31) *s_nactp = incl;
    }
    __syncthreads();
    if (act) {
        int pos = s_wbase[wid] + __popc(gm & ((1u << l) - 1u));
        s_idx[pos] = (unsigned short)tid;
        s_cval[pos] = c;
    }
    __syncthreads();

    int nact = *s_nactp;

    // phase 1: LIF trains + spike-count histogram
    int myCnt = 0;
    if (tid < nact) {
        float cc = s_cval[tid];
        float mem = 0.f, sp = 0.f;
        unsigned tr0 = 0, tr1 = 0, tr2 = 0, tr3 = 0;
        #pragma unroll
        for (int u = 0; u < 32; u++) {
            mem = __fmaf_rn(0.95f, mem, cc) - sp;
            bool s = mem > 1.0f; sp = s ? 1.0f : 0.0f;
            tr0 |= ((unsigned)s) << u;
        }
        #pragma unroll
        for (int u = 0; u < 32; u++) {
            mem = __fmaf_rn(0.95f, mem, cc) - sp;
            bool s = mem > 1.0f; sp = s ? 1.0f : 0.0f;
            tr1 |= ((unsigned)s) << u;
        }
        #pragma unroll
        for (int u = 0; u < 32; u++) {
            mem = __fmaf_rn(0.95f, mem, cc) - sp;
            bool s = mem > 1.0f; sp = s ? 1.0f : 0.0f;
            tr2 |= ((unsigned)s) << u;
        }
        #pragma unroll
        for (int u = 0; u < 4; u++) {
            mem = __fmaf_rn(0.95f, mem, cc) - sp;
            bool s = mem > 1.0f; sp = s ? 1.0f : 0.0f;
            tr3 |= ((unsigned)s) << u;
        }
        s_train[tid] = make_uint4(tr0, tr1, tr2, tr3);
        myCnt = __popc(tr0) + __popc(tr1) + __popc(tr2) + __popc(tr3);
        atomicAdd(&s_hist[myCnt], 1);
    }
    __syncthreads();

    if (tid == 0) {
        int run = 0;
        for (int cb = 0; cb <= 100; cb++) { s_cur[cb] = run; run += s_hist[cb]; }
    }
    __syncthreads();
    if (tid < nact) {
        int pos = atomicAdd(&s_cur[myCnt], 1);  // order in bin arbitrary: sums order-free
        s_order[pos] = (unsigned short)tid;
    }
    __syncthreads();

    // phase 2: quad scatter
    {
        int r = l & 7, g = l >> 3;
        int nquads = (nact + 3) >> 2;
        const int4* wq = (const int4*)g_w2Q;
        int* basep = s_acc + (r + 8 * g);

        for (int q = wid; q < nquads; q += 32) {
            int sIdx = 4 * q + g;
            int slot = (sIdx < nact) ? (int)s_order[sIdx] : 0;
            bool live = (sIdx < nact);
            unsigned hh = (unsigned)s_idx[slot];
            int4 va = wq[hh * 16 + r * 2];
            int4 vb = wq[hh * 16 + r * 2 + 1];
            int v0 = va.x, v1 = va.y, v2 = va.z, v3 = va.w;
            int v4 = vb.x, v5 = vb.y, v6 = vb.z, v7 = vb.w;
            if (g & 1) { int t0 = v0; v0 = v1; v1 = v2; v2 = v3; v3 = v4;
                         v4 = v5; v5 = v6; v6 = v7; v7 = t0; }
            if (g & 2) { int t0 = v0, t1 = v1; v0 = v2; v1 = v3; v2 = v4; v3 = v5;
                         v4 = v6; v5 = v7; v6 = t0; v7 = t1; }

            const unsigned* trw = (const unsigned*)&s_train[slot];
            #pragma unroll
            for (int w = 0; w < 4; w++) {
                unsigned m = live ? trw[w] : 0u;
                int* bw = basep + w * 4096;    // t = 32w + tb
                while (__any_sync(0xffffffffu, m)) {
                    if (m) {
                        int tb = __ffs(m) - 1; m &= m - 1;
                        int* a = bw + tb * 128;
                        atomicAdd(a,      v0);  atomicAdd(a + 8,  v1);
                        atomicAdd(a + 16, v2);  atomicAdd(a + 24, v3);
                        atomicAdd(a + 32, v4);  atomicAdd(a + 40, v5);
                        atomicAdd(a + 48, v6);  atomicAdd(a + 56, v7);
                    }
                }
            }
        }
    }
    __syncthreads();

    // phase 3: fold alias columns + layer-2 LIF scan
    if (tid < 64) {
        float b2o = b2[tid];
        float mem = 0.f, sp = 0.f, sum = 0.f;
        #pragma unroll 4
        for (int t = 0; t < 100; t++) {
            int raw = s_acc[t * 128 + tid] + s_acc[t * 128 + 64 + tid];
            float cur = __fmaf_rn((float)raw, W2_INVSCALE, b2o);
            mem = __fmaf_rn(0.95f, mem, cur) - sp;
            bool s = mem > 1.0f;
            sp = s ? 1.0f : 0.0f;
            sum += sp;
        }
        g_snn[b * 64 + tid] = sum * 0.01f;
    }
}

__global__ __launch_bounds__(256) void nn_kernel(const float* __restrict__ x,
                                                 const float* __restrict__ w1,
                                                 const float* __restrict__ b1,
                                                 const float* __restrict__ b2,
                                                 int B) {
    __shared__ float s_h[8 * 1024];
    __shared__ float s_f[8][5];
    int b0 = blockIdx.x * 8, tid = threadIdx.x;

    if (tid < 40) s_f[tid / 5][tid % 5] = x[(b0 + tid / 5) * 105 + tid % 5];
    __syncthreads();

    for (int j = 0; j < 4; j++) {
        int h = tid + 256 * j;
        const float* wr = w1 + h * 5;
        float w0 = wr[0], w1v = wr[1], w2v = wr[2], w3 = wr[3], w4 = wr[4];
        float bb = b1[h];
        #pragma unroll
        for (int r = 0; r < 8; r++) {
            float v = bb + s_f[r][0] * w0 + s_f[r][1] * w1v + s_f[r][2] * w2v +
                      s_f[r][3] * w3 + s_f[r][4] * w4;
            s_h[r * 1024 + h] = v > 0.f ? v : 0.f;
        }
    }
    __syncthreads();

    int o = tid & 63, rg = tid >> 6;
    float a0 = 0.f, a1 = 0.f;
    const float* h0 = s_h + (rg * 2) * 1024;
    const float* h1 = s_h + (rg * 2 + 1) * 1024;
    for (int h = 0; h < 1024; h++) {
        float w = g_nnw2T[h * 64 + o];
        a0 += w * h0[h];
        a1 += w * h1[h];
    }
    float bo = b2[o];
    g_nn[(b0 + rg * 2) * 64 + o]     = a0 + bo;
    g_nn[(b0 + rg * 2 + 1) * 64 + o] = a1 + bo;
}

#define CNN_SMEM_BYTES ((25600 + 16 * 102) * 4)

__global__ __launch_bounds__(256, 2) void cnn_kernel(const float* __restrict__ x,
                                                     const float* __restrict__ cw,
                                                     const float* __restrict__ cb,
                                                     const float* __restrict__ fcb,
                                                     int B) {
    extern __shared__ float sm[];
    float* s_p    = sm;
    float* s_wave = sm + 25600;
    __shared__ float s_cw[96];
    __shared__ float s_cb[32];

    int b0 = blockIdx.x * 16, tid = threadIdx.x;

    if (tid < 96) s_cw[tid] = cw[tid];
    if (tid < 32) s_cb[tid] = cb[tid];
    for (int i = tid; i < 16 * 102; i += 256) {
        int r = i / 102, q = i % 102;
        float v = 0.f;
        if (q >= 1 && q <= 100) v = x[(b0 + r) * 105 + 4 + q];
        s_wave[i] = v;
    }
    __syncthreads();

    for (int i = tid; i < 25600; i += 256) {
        int r = i & 15, pos = i >> 4;
        int ch = pos / 50, j = pos - ch * 50;
        const float* wv = s_wave + r * 102 + 2 * j;
        float w0 = s_cw[ch * 3], w1 = s_cw[ch * 3 + 1], w2 = s_cw[ch * 3 + 2];
        float bb = s_cb[ch];
        float c0 = bb + wv[0] * w0 + wv[1] * w1 + wv[2] * w2;
        float c1 = bb + wv[1] * w0 + wv[2] * w1 + wv[3] * w2;
        float m = fmaxf(c0, c1);
        s_p[pos * 16 + r] = m > 0.f ? m : 0.f;
    }
    __syncthreads();

    int og = tid & 127, kh = tid >> 7;
    unsigned long long a[16];
    #pragma unroll
    for (int q = 0; q < 16; q++) a[q] = 0ull;

    int kbeg = kh * 800;
    const float2* fp = (const float2*)g_fcT + (size_t)kbeg * 128 + og;
    const ulonglong2* rp = (const ulonglong2*)s_p + kbeg * 4;

    for (int kk = 0; kk < 800; kk += 4) {
        float2 w0 = fp[0], w1 = fp[128], w2 = fp[256], w3 = fp[384];
        fp += 512;
        unsigned long long W0[4], W1[4];
        asm("mov.b64 %0, {%1, %1};" : "=l"(W0[0]) : "r"(__float_as_uint(w0.x)));
        asm("mov.b64 %0, {%1, %1};" : "=l"(W1[0]) : "r"(__float_as_uint(w0.y)));
        asm("mov.b64 %0, {%1, %1};" : "=l"(W0[1]) : "r"(__float_as_uint(w1.x)));
        asm("mov.b64 %0, {%1, %1};" : "=l"(W1[1]) : "r"(__float_as_uint(w1.y)));
        asm("mov.b64 %0, {%1, %1};" : "=l"(W0[2]) : "r"(__float_as_uint(w2.x)));
        asm("mov.b64 %0, {%1, %1};" : "=l"(W1[2]) : "r"(__float_as_uint(w2.y)));
        asm("mov.b64 %0, {%1, %1};" : "=l"(W0[3]) : "r"(__float_as_uint(w3.x)));
        asm("mov.b64 %0, {%1, %1};" : "=l"(W1[3]) : "r"(__float_as_uint(w3.y)));
        #pragma unroll
        for (int u = 0; u < 4; u++) {
            #pragma unroll
            for (int m2 = 0; m2 < 4; m2++) {
                ulonglong2 v = rp[u * 4 + m2];
                asm("fma.rn.f32x2 %0, %1, %2, %0;" : "+l"(a[2 * m2])         : "l"(v.x), "l"(W0[u]));
                asm("fma.rn.f32x2 %0, %1, %2, %0;" : "+l"(a[2 * m2 + 1])     : "l"(v.y), "l"(W0[u]));
                asm("fma.rn.f32x2 %0, %1, %2, %0;" : "+l"(a[8 + 2 * m2])     : "l"(v.x), "l"(W1[u]));
                asm("fma.rn.f32x2 %0, %1, %2, %0;" : "+l"(a[8 + 2 * m2 + 1]) : "l"(v.y), "l"(W1[u]));
            }
        }
        rp += 16;
    }

    int o0 = og * 2;
    if (kh == 1) {
        #pragma unroll
        for (int q = 0; q < 8; q++) {
            float lo0 = __uint_as_float((unsigned)(a[q] & 0xffffffffull));
            float hi0 = __uint_as_float((unsigned)(a[q] >> 32));
            float lo1 = __uint_as_float((unsigned)(a[8 + q] & 0xffffffffull));
            float hi1 = __uint_as_float((unsigned)(a[8 + q] >> 32));
            *(float2*)(g_cnn + (b0 + 2 * q) * 256 + o0)     = make_float2(lo0, lo1);
            *(float2*)(g_cnn + (b0 + 2 * q + 1) * 256 + o0) = make_float2(hi0, hi1);
        }
    }
    __syncthreads();
    if (kh == 0) {
        float fb0 = fcb[o0], fb1 = fcb[o0 + 1];
        #pragma unroll
        for (int q = 0; q < 8; q++) {
            float lo0 = __uint_as_float((unsigned)(a[q] & 0xffffffffull));
            float hi0 = __uint_as_float((unsigned)(a[q] >> 32));
            float lo1 = __uint_as_float((unsigned)(a[8 + q] & 0xffffffffull));
            float hi1 = __uint_as_float((unsigned)(a[8 + q] >> 32));
            float2* p0 = (float2*)(g_cnn + (b0 + 2 * q) * 256 + o0);
            float2* p1 = (float2*)(g_cnn + (b0 + 2 * q + 1) * 256 + o0);
            float2 v0 = *p0, v1 = *p1;
            *p0 = make_float2(lo0 + fb0 + v0.x, lo1 + fb1 + v0.y);
            *p1 = make_float2(hi0 + fb0 + v1.x, hi1 + fb1 + v1.y);
        }
    }
}

__global__ __launch_bounds__(256) void comb_kernel(const float* __restrict__ cbias,
                                                   float* __restrict__ out,
                                                   int B) {
    __shared__ float s_c[16 * 384];
    int b0 = blockIdx.x * 16, tid = threadIdx.x;

    for (int i = tid; i < 16 * 64; i += 256) {
        int r = i >> 6, o = i & 63;
        s_c[r * 384 + o]      = g_snn[(b0 + r) * 64 + o];
        s_c[r * 384 + 64 + o] = g_nn[(b0 + r) * 64 + o];
    }
    for (int i = tid; i < 16 * 256; i += 256) {
        int r = i >> 8, o = i & 255;
        s_c[r * 384 + 128 + o] = g_cnn[(b0 + r) * 256 + o];
    }
    __syncthreads();

    int o = tid & 63, rg = tid >> 6;
    float a[4] = {0.f, 0.f, 0.f, 0.f};
    for (int c = 0; c < 384; c++) {
        float w = g_combT[c * 64 + o];
        const float* pr = s_c + (rg * 4) * 384 + c;
        a[0] += w * pr[0];
        a[1] += w * pr[384];
        a[2] += w * pr[2 * 384];
        a[3] += w * pr[3 * 384];
    }
    float bo = cbias[o];
    #pragma unroll
    for (int q = 0; q < 4; q++)
        out[(b0 + rg * 4 + q) * 64 + o] = a[q] + bo;
}

extern "C" void kernel_launch(void* const* d_in, const int* in_sizes, int n_in,
                              void* d_out, int out_size) {
    const float* x      = (const float*)d_in[0];
    const float* snn_w1 = (const float*)d_in[1];
    const float* snn_b1 = (const float*)d_in[2];
    const float* snn_w2 = (const float*)d_in[3];
    const float* snn_b2 = (const float*)d_in[4];
    const float* nn_w1  = (const float*)d_in[5];
    const float* nn_b1  = (const float*)d_in[6];
    const float* nn_w2  = (const float*)d_in[7];
    const float* nn_b2  = (const float*)d_in[8];
    const float* conv_w = (const float*)d_in[9];
    const float* conv_b = (const float*)d_in[10];
    const float* fc_w   = (const float*)d_in[11];
    const float* fc_b   = (const float*)d_in[12];
    const float* comb_w = (const float*)d_in[13];
    const float* comb_b = (const float*)d_in[14];

    int B = in_sizes[0] / 105;

    static cudaStream_t s1 = nullptr, s2 = nullptr;
    static cudaEvent_t  e0 = nullptr, e1 = nullptr, e2 = nullptr;
    static bool attr_set = false;
    if (!s1) {
        cudaStreamCreateWithFlags(&s1, cudaStreamNonBlocking);
        cudaStreamCreateWithFlags(&s2, cudaStreamNonBlocking);
        cudaEventCreateWithFlags(&e0, cudaEventDisableTiming);
        cudaEventCreateWithFlags(&e1, cudaEventDisableTiming);
        cudaEventCreateWithFlags(&e2, cudaEventDisableTiming);
    }
    if (!attr_set) {
        cudaFuncSetAttribute(cnn_kernel, cudaFuncAttributeMaxDynamicSharedMemorySize,
                             CNN_SMEM_BYTES);
        cudaFuncSetAttribute(snn_kernel, cudaFuncAttributeMaxDynamicSharedMemorySize,
                             SNN_SMEM_BYTES);
        attr_set = true;
    }

    prep_kernel<<<1600, 256>>>(snn_w2, nn_w2, fc_w, comb_w);
    cudaEventRecord(e0, 0);

    cudaStreamWaitEvent(s1, e0, 0);
    cnn_kernel<<<B / 16, 256, CNN_SMEM_BYTES, s1>>>(x, conv_w, conv_b, fc_b, B);
    cudaEventRecord(e1, s1);

    cudaStreamWaitEvent(s2, e0, 0);
    nn_kernel<<<B / 8, 256, 0, s2>>>(x, nn_w1, nn_b1, nn_b2, B);
    cudaEventRecord(e2, s2);

    snn_kernel<<<B, 1024, SNN_SMEM_BYTES>>>(x, snn_w1, snn_b1, snn_b2, B);

    cudaStreamWaitEvent(0, e1, 0);
    cudaStreamWaitEvent(0, e2, 0);
    comb_kernel<<<B / 16, 256>>>(comb_b, (float*)d_out, B);
}

// round 16
// speedup vs baseline: 1.1091x; 1.0273x over previous
#include <cuda_runtime.h>
#include <cuda_bf16.h>
#include <cstdint>

#define B_MAX 16384

__device__ int   g_w2Q[1024 * 64];    // [h*64 + r*8 + j] = rn(w2[r+8j][h]*2^24)
__device__ float g_nnw2T[1024 * 64];  // [h][o]
__device__ float g_fcT[1600 * 256];   // [k][o]
__device__ float g_combT[384 * 64];   // [c][o]
__device__ float g_snn[B_MAX * 64];
__device__ float g_nn[B_MAX * 64];
__device__ float g_cnn[B_MAX * 256];

#define W2_SCALE    16777216.0f
#define W2_INVSCALE 5.9604645e-8f

#define SPLAT64(dst, s) asm("mov.b64 %0, {%1, %1};" : "=l"(dst) : "r"(__float_as_uint(s)))
#define FMA_X2(acc, v, w) asm("fma.rn.f32x2 %0, %1, %2, %0;" : "+l"(acc) : "l"(v), "l"(w))
#define ADD_X2(acc, v)    asm("add.rn.f32x2 %0, %1, %0;"     : "+l"(acc) : "l"(v))
#define LO32(u) __uint_as_float((unsigned)((u) & 0xffffffffull))
#define HI32(u) __uint_as_float((unsigned)((u) >> 32))

__global__ void prep_kernel(const float* __restrict__ snn_w2,
                            const float* __restrict__ nn_w2,
                            const float* __restrict__ fc_w,
                            const float* __restrict__ comb_w) {
    int i = blockIdx.x * blockDim.x + threadIdx.x;
    if (i < 1024 * 64) {
        int h = i >> 6, j6 = i & 63;
        int o = (j6 >> 3) + 8 * (j6 & 7);
        g_w2Q[i]   = __float2int_rn(snn_w2[o * 1024 + h] * W2_SCALE);
        g_nnw2T[i] = nn_w2[(i & 63) * 1024 + h];
    }
    if (i < 1600 * 256) g_fcT[i] = fc_w[(i & 255) * 1600 + (i >> 8)];
    if (i < 384 * 64)   g_combT[i] = comb_w[(i & 63) * 384 + (i >> 6)];
}

// ---------------- SNN (unchanged from R15: 779us, bit-stable output) ---------
#define SNN_SMEM_BYTES (19224 * 4)

__global__ __launch_bounds__(1024, 2) void snn_kernel(const float* __restrict__ x,
                                                      const float* __restrict__ w1,
                                                      const float* __restrict__ b1,
                                                      const float* __restrict__ b2,
                                                      int B) {
    extern __shared__ int dsm[];
    int*            s_acc   = dsm;                            // [100][128]
    uint4*          s_train = (uint4*)(dsm + 12800);          // [1024]
    unsigned short* s_idx   = (unsigned short*)(dsm + 16896); // [1024]
    float*          s_cval  = (float*)(dsm + 17408);          // [1024]
    unsigned short* s_order = (unsigned short*)(dsm + 18432); // [1024]
    int*            s_hist  = dsm + 18944;                    // [104]
    int*            s_cur   = dsm + 19048;                    // [104]
    unsigned*       s_gm    = (unsigned*)(dsm + 19152);
    int*            s_wbase = dsm + 19184;
    int*            s_nactp = dsm + 19216;
    float*          s_feats = (float*)(dsm + 19217);

    int b = blockIdx.x, tid = threadIdx.x, wid = tid >> 5, l = tid & 31;

    if (tid < 5) s_feats[tid] = x[b * 105 + tid];
    __syncthreads();

    float f0 = s_feats[0], f1 = s_feats[1], f2 = s_feats[2],
          f3 = s_feats[3], f4 = s_feats[4];
    const float* wr = w1 + tid * 5;
    float c = b1[tid] + f0 * wr[0] + f1 * wr[1] + f2 * wr[2] + f3 * wr[3] + f4 * wr[4];
    bool act = c > 0.049995f;
    unsigned gm = __ballot_sync(0xffffffffu, act);
    if (l == 0) s_gm[wid] = gm;

    for (int i = tid; i < 12800; i += 1024) s_acc[i] = 0;
    if (tid < 104) s_hist[tid] = 0;
    __syncthreads();

    if (tid < 32) {
        int cnt = __popc(s_gm[tid]);
        int incl = cnt;
        #pragma unroll
        for (int d = 1; d < 32; d <<= 1) {
            int v = __shfl_up_sync(0xffffffffu, incl, d);
            if (tid >= d) incl += v;
        }
        s_wbase[tid] = incl - cnt;
        if (tid == 31) *s_nactp = incl;
    }
    __syncthreads();
    if (act) {
        int pos = s_wbase[wid] + __popc(gm & ((1u << l) - 1u));
        s_idx[pos] = (unsigned short)tid;
        s_cval[pos] = c;
    }
    __syncthreads();

    int nact = *s_nactp;

    int myCnt = 0;
    if (tid < nact) {
        float cc = s_cval[tid];
        float mem = 0.f, sp = 0.f;
        unsigned tr0 = 0, tr1 = 0, tr2 = 0, tr3 = 0;
        #pragma unroll
        for (int u = 0; u < 32; u++) {
            mem = __fmaf_rn(0.95f, mem, cc) - sp;
            bool s = mem > 1.0f; sp = s ? 1.0f : 0.0f;
            tr0 |= ((unsigned)s) << u;
        }
        #pragma unroll
        for (int u = 0; u < 32; u++) {
            mem = __fmaf_rn(0.95f, mem, cc) - sp;
            bool s = mem > 1.0f; sp = s ? 1.0f : 0.0f;
            tr1 |= ((unsigned)s) << u;
        }
        #pragma unroll
        for (int u = 0; u < 32; u++) {
            mem = __fmaf_rn(0.95f, mem, cc) - sp;
            bool s = mem > 1.0f; sp = s ? 1.0f : 0.0f;
            tr2 |= ((unsigned)s) << u;
        }
        #pragma unroll
        for (int u = 0; u < 4; u++) {
            mem = __fmaf_rn(0.95f, mem, cc) - sp;
            bool s = mem > 1.0f; sp = s ? 1.0f : 0.0f;
            tr3 |= ((unsigned)s) << u;
        }
        s_train[tid] = make_uint4(tr0, tr1, tr2, tr3);
        myCnt = __popc(tr0) + __popc(tr1) + __popc(tr2) + __popc(tr3);
        atomicAdd(&s_hist[myCnt], 1);
    }
    __syncthreads();

    if (tid == 0) {
        int run = 0;
        for (int cb = 0; cb <= 100; cb++) { s_cur[cb] = run; run += s_hist[cb]; }
    }
    __syncthreads();
    if (tid < nact) {
        int pos = atomicAdd(&s_cur[myCnt], 1);
        s_order[pos] = (unsigned short)tid;
    }
    __syncthreads();

    {
        int r = l & 7, g = l >> 3;
        int nquads = (nact + 3) >> 2;
        const int4* wq = (const int4*)g_w2Q;
        int* basep = s_acc + (r + 8 * g);

        for (int q = wid; q < nquads; q += 32) {
            int sIdx = 4 * q + g;
            int slot = (sIdx < nact) ? (int)s_order[sIdx] : 0;
            bool live = (sIdx < nact);
            unsigned hh = (unsigned)s_idx[slot];
            int4 va = wq[hh * 16 + r * 2];
            int4 vb = wq[hh * 16 + r * 2 + 1];
            int v0 = va.x, v1 = va.y, v2 = va.z, v3 = va.w;
            int v4 = vb.x, v5 = vb.y, v6 = vb.z, v7 = vb.w;
            if (g & 1) { int t0 = v0; v0 = v1; v1 = v2; v2 = v3; v3 = v4;
                         v4 = v5; v5 = v6; v6 = v7; v7 = t0; }
            if (g & 2) { int t0 = v0, t1 = v1; v0 = v2; v1 = v3; v2 = v4; v3 = v5;
                         v4 = v6; v5 = v7; v6 = t0; v7 = t1; }

            const unsigned* trw = (const unsigned*)&s_train[slot];
            #pragma unroll
            for (int w = 0; w < 4; w++) {
                unsigned m = live ? trw[w] : 0u;
                int* bw = basep + w * 4096;
                while (__any_sync(0xffffffffu, m)) {
                    if (m) {
                        int tb = __ffs(m) - 1; m &= m - 1;
                        int* a = bw + tb * 128;
                        atomicAdd(a,      v0);  atomicAdd(a + 8,  v1);
                        atomicAdd(a + 16, v2);  atomicAdd(a + 24, v3);
                        atomicAdd(a + 32, v4);  atomicAdd(a + 40, v5);
                        atomicAdd(a + 48, v6);  atomicAdd(a + 56, v7);
                    }
                }
            }
        }
    }
    __syncthreads();

    if (tid < 64) {
        float b2o = b2[tid];
        float mem = 0.f, sp = 0.f, sum = 0.f;
        #pragma unroll 4
        for (int t = 0; t < 100; t++) {
            int raw = s_acc[t * 128 + tid] + s_acc[t * 128 + 64 + tid];
            float cur = __fmaf_rn((float)raw, W2_INVSCALE, b2o);
            mem = __fmaf_rn(0.95f, mem, cur) - sp;
            bool s = mem > 1.0f;
            sp = s ? 1.0f : 0.0f;
            sum += sp;
        }
        g_snn[b * 64 + tid] = sum * 0.01f;
    }
}

// ---------------- NN: 8 rows/block, f32x2 FC, 8-way k-split -------------------
__global__ __launch_bounds__(256) void nn_kernel(const float* __restrict__ x,
                                                 const float* __restrict__ w1,
                                                 const float* __restrict__ b1,
                                                 const float* __restrict__ b2,
                                                 int B) {
    __shared__ float s_h[1024 * 8];   // [h][r] (32B per h)
    __shared__ float s_f[8][5];
    int b0 = blockIdx.x * 8, tid = threadIdx.x;

    if (tid < 40) s_f[tid / 5][tid % 5] = x[(b0 + tid / 5) * 105 + tid % 5];
    __syncthreads();

    // hidden layer, transposed store (2 STS.128 per h)
    for (int j = 0; j < 4; j++) {
        int h = tid + 256 * j;
        const float* wr = w1 + h * 5;
        float w0 = wr[0], w1v = wr[1], w2v = wr[2], w3 = wr[3], w4 = wr[4];
        float bb = b1[h];
        float v[8];
        #pragma unroll
        for (int r = 0; r < 8; r++) {
            float t = bb + s_f[r][0] * w0 + s_f[r][1] * w1v + s_f[r][2] * w2v +
                      s_f[r][3] * w3 + s_f[r][4] * w4;
            v[r] = t > 0.f ? t : 0.f;
        }
        float4* dst = (float4*)(s_h + h * 8);
        dst[0] = make_float4(v[0], v[1], v[2], v[3]);
        dst[1] = make_float4(v[4], v[5], v[6], v[7]);
    }
    __syncthreads();

    // FC 1024->64: thread = (o-pair og, k-eighth kh), 128 k each
    int og = tid & 31, kh = tid >> 5;
    unsigned long long a[8];
    #pragma unroll
    for (int q = 0; q < 8; q++) a[q] = 0ull;

    int kbeg = kh * 128;
    const float2* wp = (const float2*)g_nnw2T + (size_t)kbeg * 32 + og;
    const ulonglong2* hp = (const ulonglong2*)s_h + kbeg * 2;

    #pragma unroll 2
    for (int k = 0; k < 128; k++) {
        float2 w = wp[0]; wp += 32;
        unsigned long long W0, W1;
        SPLAT64(W0, w.x); SPLAT64(W1, w.y);
        ulonglong2 u0 = hp[0], u1 = hp[1]; hp += 2;
        FMA_X2(a[0], u0.x, W0); FMA_X2(a[1], u0.y, W0);
        FMA_X2(a[2], u1.x, W0); FMA_X2(a[3], u1.y, W0);
        FMA_X2(a[4], u0.x, W1); FMA_X2(a[5], u0.y, W1);
        FMA_X2(a[6], u1.x, W1); FMA_X2(a[7], u1.y, W1);
    }
    __syncthreads();   // all reads of s_h done

    // partial fold in smem (overlay s_h), deterministic order kh=1..7
    unsigned long long* s_part = (unsigned long long*)s_h;
    if (kh > 0) {
        unsigned long long* dst = s_part + ((size_t)(kh - 1) * 32 + og) * 8;
        #pragma unroll
        for (int q = 0; q < 8; q++) dst[q] = a[q];
    }
    __syncthreads();
    if (kh == 0) {
        #pragma unroll
        for (int p = 0; p < 7; p++) {
            const unsigned long long* src = s_part + ((size_t)p * 32 + og) * 8;
            #pragma unroll
            for (int q = 0; q < 8; q++) ADD_X2(a[q], src[q]);
        }
        int o0 = og * 2;
        float fb0 = b2[o0], fb1 = b2[o0 + 1];
        #pragma unroll
        for (int q = 0; q < 4; q++) {
            // a[q]: rows (2q,2q+1) of output o0; a[4+q]: same rows of o0+1
            *(float2*)(g_nn + (b0 + 2 * q) * 64 + o0) =
                make_float2(LO32(a[q]) + fb0, LO32(a[4 + q]) + fb1);
            *(float2*)(g_nn + (b0 + 2 * q + 1) * 64 + o0) =
                make_float2(HI32(a[q]) + fb0, HI32(a[4 + q]) + fb1);
        }
    }
}

// ---------------- CNN: 16 rows/block, 4 outputs/thread, 4-way k-split --------
#define CNN_SMEM_BYTES ((25600 + 16 * 102) * 4)

__global__ __launch_bounds__(256, 2) void cnn_kernel(const float* __restrict__ x,
                                                     const float* __restrict__ cw,
                                                     const float* __restrict__ cb,
                                                     const float* __restrict__ fcb,
                                                     int B) {
    extern __shared__ float sm[];
    float* s_p    = sm;            // [k][16]
    float* s_wave = sm + 25600;
    __shared__ float s_cw[96];
    __shared__ float s_cb[32];

    int b0 = blockIdx.x * 16, tid = threadIdx.x;

    if (tid < 96) s_cw[tid] = cw[tid];
    if (tid < 32) s_cb[tid] = cb[tid];
    for (int i = tid; i < 16 * 102; i += 256) {
        int r = i / 102, q = i % 102;
        float v = 0.f;
        if (q >= 1 && q <= 100) v = x[(b0 + r) * 105 + 4 + q];
        s_wave[i] = v;
    }
    __syncthreads();

    for (int i = tid; i < 25600; i += 256) {
        int r = i & 15, pos = i >> 4;
        int ch = pos / 50, j = pos - ch * 50;
        const float* wv = s_wave + r * 102 + 2 * j;
        float w0 = s_cw[ch * 3], w1 = s_cw[ch * 3 + 1], w2 = s_cw[ch * 3 + 2];
        float bb = s_cb[ch];
        float c0 = bb + wv[0] * w0 + wv[1] * w1 + wv[2] * w2;
        float c1 = bb + wv[1] * w0 + wv[2] * w1 + wv[3] * w2;
        float m = fmaxf(c0, c1);
        s_p[pos * 16 + r] = m > 0.f ? m : 0.f;
    }
    __syncthreads();

    // FC 1600->256: thread = (output-quad oq, k-quarter kh); 400 k each
    int oq = tid & 63, kh = tid >> 6;
    unsigned long long a[32];         // a[oi*8+q]: output 4oq+oi, rows (2q,2q+1)
    #pragma unroll
    for (int q = 0; q < 32; q++) a[q] = 0ull;

    int kbeg = kh * 400;
    const float4* fp = (const float4*)(g_fcT + (size_t)kbeg * 256) + oq;
    const ulonglong2* rp = (const ulonglong2*)s_p + kbeg * 4;

    #pragma unroll 2
    for (int kk = 0; kk < 400; kk++) {
        float4 w = fp[0]; fp += 64;
        unsigned long long W0, W1, W2, W3;
        SPLAT64(W0, w.x); SPLAT64(W1, w.y); SPLAT64(W2, w.z); SPLAT64(W3, w.w);
        ulonglong2 v0 = rp[0], v1 = rp[1], v2 = rp[2], v3 = rp[3]; rp += 4;
        FMA_X2(a[0],  v0.x, W0); FMA_X2(a[1],  v0.y, W0);
        FMA_X2(a[2],  v1.x, W0); FMA_X2(a[3],  v1.y, W0);
        FMA_X2(a[4],  v2.x, W0); FMA_X2(a[5],  v2.y, W0);
        FMA_X2(a[6],  v3.x, W0); FMA_X2(a[7],  v3.y, W0);
        FMA_X2(a[8],  v0.x, W1); FMA_X2(a[9],  v0.y, W1);
        FMA_X2(a[10], v1.x, W1); FMA_X2(a[11], v1.y, W1);
        FMA_X2(a[12], v2.x, W1); FMA_X2(a[13], v2.y, W1);
        FMA_X2(a[14], v3.x, W1); FMA_X2(a[15], v3.y, W1);
        FMA_X2(a[16], v0.x, W2); FMA_X2(a[17], v0.y, W2);
        FMA_X2(a[18], v1.x, W2); FMA_X2(a[19], v1.y, W2);
        FMA_X2(a[20], v2.x, W2); FMA_X2(a[21], v2.y, W2);
        FMA_X2(a[22], v3.x, W2); FMA_X2(a[23], v3.y, W2);
        FMA_X2(a[24], v0.x, W3); FMA_X2(a[25], v0.y, W3);
        FMA_X2(a[26], v1.x, W3); FMA_X2(a[27], v1.y, W3);
        FMA_X2(a[28], v2.x, W3); FMA_X2(a[29], v2.y, W3);
        FMA_X2(a[30], v3.x, W3); FMA_X2(a[31], v3.y, W3);
    }
    __syncthreads();   // all reads of s_p done

    // partial fold in smem (overlay s_p; 192*32*8B = 48KB < 102KB)
    unsigned long long* s_part = (unsigned long long*)sm;
    if (kh > 0) {
        unsigned long long* dst = s_part + ((size_t)(kh - 1) * 64 + oq) * 32;
        #pragma unroll
        for (int q = 0; q < 32; q++) dst[q] = a[q];
    }
    __syncthreads();
    if (kh == 0) {
        #pragma unroll
        for (int p = 0; p < 3; p++) {
            const unsigned long long* src = s_part + ((size_t)p * 64 + oq) * 32;
            #pragma unroll
            for (int q = 0; q < 32; q++) ADD_X2(a[q], src[q]);
        }
        int o0 = oq * 4;
        float fb0 = fcb[o0], fb1 = fcb[o0 + 1], fb2 = fcb[o0 + 2], fb3 = fcb[o0 + 3];
        #pragma unroll
        for (int q = 0; q < 8; q++) {
            *(float4*)(g_cnn + (b0 + 2 * q) * 256 + o0) = make_float4(
                LO32(a[q]) + fb0, LO32(a[8 + q]) + fb1,
                LO32(a[16 + q]) + fb2, LO32(a[24 + q]) + fb3);
            *(float4*)(g_cnn + (b0 + 2 * q + 1) * 256 + o0) = make_float4(
                HI32(a[q]) + fb0, HI32(a[8 + q]) + fb1,
                HI32(a[16 + q]) + fb2, HI32(a[24 + q]) + fb3);
        }
    }
}

// ---------------- combiner (unchanged) ----------------------------------------
__global__ __launch_bounds__(256) void comb_kernel(const float* __restrict__ cbias,
                                                   float* __restrict__ out,
                                                   int B) {
    __shared__ float s_c[16 * 384];
    int b0 = blockIdx.x * 16, tid = threadIdx.x;

    for (int i = tid; i < 16 * 64; i += 256) {
        int r = i >> 6, o = i & 63;
        s_c[r * 384 + o]      = g_snn[(b0 + r) * 64 + o];
        s_c[r * 384 + 64 + o] = g_nn[(b0 + r) * 64 + o];
    }
    for (int i = tid; i < 16 * 256; i += 256) {
        int r = i >> 8, o = i & 255;
        s_c[r * 384 + 128 + o] = g_cnn[(b0 + r) * 256 + o];
    }
    __syncthreads();

    int o = tid & 63, rg = tid >> 6;
    float a[4] = {0.f, 0.f, 0.f, 0.f};
    for (int c = 0; c < 384; c++) {
        float w = g_combT[c * 64 + o];
        const float* pr = s_c + (rg * 4) * 384 + c;
        a[0] += w * pr[0];
        a[1] += w * pr[384];
        a[2] += w * pr[2 * 384];
        a[3] += w * pr[3 * 384];
    }
    float bo = cbias[o];
    #pragma unroll
    for (int q = 0; q < 4; q++)
        out[(b0 + rg * 4 + q) * 64 + o] = a[q] + bo;
}

extern "C" void kernel_launch(void* const* d_in, const int* in_sizes, int n_in,
                              void* d_out, int out_size) {
    const float* x      = (const float*)d_in[0];
    const float* snn_w1 = (const float*)d_in[1];
    const float* snn_b1 = (const float*)d_in[2];
    const float* snn_w2 = (const float*)d_in[3];
    const float* snn_b2 = (const float*)d_in[4];
    const float* nn_w1  = (const float*)d_in[5];
    const float* nn_b1  = (const float*)d_in[6];
    const float* nn_w2  = (const float*)d_in[7];
    const float* nn_b2  = (const float*)d_in[8];
    const float* conv_w = (const float*)d_in[9];
    const float* conv_b = (const float*)d_in[10];
    const float* fc_w   = (const float*)d_in[11];
    const float* fc_b   = (const float*)d_in[12];
    const float* comb_w = (const float*)d_in[13];
    const float* comb_b = (const float*)d_in[14];

    int B = in_sizes[0] / 105;

    static cudaStream_t s1 = nullptr, s2 = nullptr;
    static cudaEvent_t  e0 = nullptr, e1 = nullptr, e2 = nullptr;
    static bool attr_set = false;
    if (!s1) {
        cudaStreamCreateWithFlags(&s1, cudaStreamNonBlocking);
        cudaStreamCreateWithFlags(&s2, cudaStreamNonBlocking);
        cudaEventCreateWithFlags(&e0, cudaEventDisableTiming);
        cudaEventCreateWithFlags(&e1, cudaEventDisableTiming);
        cudaEventCreateWithFlags(&e2, cudaEventDisableTiming);
    }
    if (!attr_set) {
        cudaFuncSetAttribute(cnn_kernel, cudaFuncAttributeMaxDynamicSharedMemorySize,
                             CNN_SMEM_BYTES);
        cudaFuncSetAttribute(snn_kernel, cudaFuncAttributeMaxDynamicSharedMemorySize,
                             SNN_SMEM_BYTES);
        attr_set = true;
    }

    prep_kernel<<<1600, 256>>>(snn_w2, nn_w2, fc_w, comb_w);
    cudaEventRecord(e0, 0);

    cudaStreamWaitEvent(s1, e0, 0);
    cnn_kernel<<<B / 16, 256, CNN_SMEM_BYTES, s1>>>(x, conv_w, conv_b, fc_b, B);
    cudaEventRecord(e1, s1);

    cudaStreamWaitEvent(s2, e0, 0);
    nn_kernel<<<B / 8, 256, 0, s2>>>(x, nn_w1, nn_b1, nn_b2, B);
    cudaEventRecord(e2, s2);

    snn_kernel<<<B, 1024, SNN_SMEM_BYTES>>>(x, snn_w1, snn_b1, snn_b2, B);

    cudaStreamWaitEvent(0, e1, 0);
    cudaStreamWaitEvent(0, e2, 0);
    comb_kernel<<<B / 16, 256>>>(comb_b, (float*)d_out, B);
}